// round 4
// baseline (speedup 1.0000x reference)
#include <cuda_runtime.h>
#include <cuda_bf16.h>
#include <math.h>

// Scratch (no allocations allowed): per-block partials + completion counter.
// Every g_part slot used in a launch is rewritten that launch; g_count
// self-resets to 0 in the last block -> deterministic across graph replays.
#define MAX_BLOCKS 4096
__device__ float g_part[MAX_BLOCKS];
__device__ unsigned int g_count = 0;

#define TPB 256
#define ILP 16

__global__ void __launch_bounds__(TPB) nll_fused_kernel(
    const float* __restrict__ pred,          // (n, 8) fp32, channel 0 used
    const unsigned char* __restrict__ mask,  // (n,) bool (1 byte)
    float* __restrict__ out,
    int n)
{
    const int tid = blockIdx.x * TPB + threadIdx.x;
    const int stride = gridDim.x * TPB;

    float s = 0.0f;

    if (n == stride * ILP) {
        // Fast path: exactly ILP strided elements per thread.
        // Front-batch ALL 32 loads (16 pred sectors + 16 mask bytes) before
        // any compute. Lane l hits consecutive 32B sectors (pred stride =
        // 8 floats = 1 sector) -> every DRAM sector fetched is consumed.
        // __ldcs: stream / evict-first -- data is touched exactly once, so
        // don't let 134MB trash L2.
        float p[ILP];
        unsigned char m[ILP];
        #pragma unroll
        for (int k = 0; k < ILP; k++) {
            int e = tid + k * stride;
            p[k] = __ldcs(&pred[(size_t)e * 8]);
        }
        #pragma unroll
        for (int k = 0; k < ILP; k++) {
            int e = tid + k * stride;
            m[k] = __ldcs(&mask[e]);
        }
        #pragma unroll
        for (int k = 0; k < ILP; k++) {
            // log(p) if masked else log(1-p). 1-p is exact for p>=0.5
            // (Sterbenz) and <=0.5ulp otherwise: per-element error ~2e-7,
            // random sign -> invisible in the 4M-term sum at 1e-3 tolerance.
            float q = m[k] ? p[k] : 1.0f - p[k];
            s += logf(q);
        }
    } else {
        // Generic fallback (any n).
        #pragma unroll 4
        for (int i = tid; i < n; i += stride) {
            float p = __ldg(&pred[(size_t)i * 8]);
            s += mask[i] ? logf(p) : log1pf(-p);
        }
    }

    // Warp reduction.
    #pragma unroll
    for (int o = 16; o > 0; o >>= 1)
        s += __shfl_xor_sync(0xFFFFFFFFu, s, o);

    __shared__ float warp_sums[TPB / 32];
    const int lane = threadIdx.x & 31;
    const int warp = threadIdx.x >> 5;
    if (lane == 0) warp_sums[warp] = s;
    __syncthreads();

    if (warp == 0) {
        float bs = (lane < (TPB >> 5)) ? warp_sums[lane] : 0.0f;
        #pragma unroll
        for (int o = 4; o > 0; o >>= 1)
            bs += __shfl_xor_sync(0xFFFFFFFFu, bs, o);
        if (lane == 0) g_part[blockIdx.x] = bs;
    }

    // Elect the last block to finish (threadfence-reduction pattern).
    __shared__ bool is_last;
    __threadfence();
    if (threadIdx.x == 0) {
        unsigned int c = atomicAdd(&g_count, 1u);
        is_last = (c == gridDim.x - 1);
    }
    __syncthreads();

    if (is_last) {
        double d = 0.0;
        for (int i = threadIdx.x; i < (int)gridDim.x; i += TPB)
            d += (double)g_part[i];

        #pragma unroll
        for (int o = 16; o > 0; o >>= 1)
            d += __shfl_xor_sync(0xFFFFFFFFu, d, o);

        __shared__ double dwarp[TPB / 32];
        if (lane == 0) dwarp[warp] = d;
        __syncthreads();
        if (warp == 0) {
            double bd = (lane < (TPB >> 5)) ? dwarp[lane] : 0.0;
            #pragma unroll
            for (int o = 4; o > 0; o >>= 1)
                bd += __shfl_xor_sync(0xFFFFFFFFu, bd, o);
            if (lane == 0) {
                out[0] = (float)(-bd * (1.0 / 256.0));
                g_count = 0;  // self-reset for next graph replay
            }
        }
    }
}

extern "C" void kernel_launch(void* const* d_in, const int* in_sizes, int n_in,
                              void* d_out, int out_size)
{
    const float* pred = (const float*)d_in[0];
    const unsigned char* mask = (const unsigned char*)d_in[1];
    float* out = (float*)d_out;

    int n = in_sizes[1];                             // 4,194,304 expected

    int blocks = (n + TPB * ILP - 1) / (TPB * ILP);  // 1024 for n=4M
    if (blocks > MAX_BLOCKS) blocks = MAX_BLOCKS;    // fallback path handles rest
    if (blocks < 1) blocks = 1;

    nll_fused_kernel<<<blocks, TPB>>>(pred, mask, out, n);
}

// round 5
// speedup vs baseline: 1.0012x; 1.0012x over previous
#include <cuda_runtime.h>
#include <cuda_bf16.h>
#include <math.h>

// Scratch (no allocations allowed): per-block partials + completion counter.
// Every g_part slot used in a launch is rewritten that launch; g_count
// self-resets to 0 in the last block -> deterministic across graph replays.
#define MAX_BLOCKS 4096
__device__ float g_part[MAX_BLOCKS];
__device__ unsigned int g_count = 0;

#define TPB 256
#define ILP 16

// min 2 blocks/SM -> 128-reg budget: lets ptxas keep all 16 in-flight loads
// live instead of sinking them to hit a 32-reg/2048-thread occupancy target.
__global__ void __launch_bounds__(TPB, 2) nll_fused_kernel(
    const float* __restrict__ pred,          // (n, 8) fp32, channel 0 used
    const unsigned char* __restrict__ mask,  // (n,) bool (1 byte)
    float* __restrict__ out,
    int n)
{
    const int tid = blockIdx.x * TPB + threadIdx.x;
    const int stride = gridDim.x * TPB;

    float s = 0.0f;

    if (n == stride * ILP) {
        // Fast path. Lanes of a warp hit consecutive 32B sectors (pred row
        // stride = 8 floats = 1 sector) -> every DRAM sector fetched is fully
        // consumed; each warp-LDG touches only 8 lines.
        //
        // The 16 pred loads are volatile inline-PTX: ordered among
        // themselves, un-sinkable -> SASS issues all 16 LDGs before the
        // first consumer. ld.global.cs = evict-first streaming (134MB
        // touched once; don't thrash L2).
        const float* a = pred + (size_t)tid * 8;
        const size_t step = (size_t)stride * 8;

        float p[ILP];
        #pragma unroll
        for (int k = 0; k < ILP; k++) {
            asm volatile("ld.global.cs.f32 %0, [%1];"
                         : "=f"(p[k]) : "l"(a));
            a += step;
        }

        unsigned char m[ILP];
        #pragma unroll
        for (int k = 0; k < ILP; k++)
            m[k] = __ldcs(&mask[tid + k * stride]);

        #pragma unroll
        for (int k = 0; k < ILP; k++) {
            // log(p) if masked else log(1-p). 1-p is exact for p>=0.5
            // (Sterbenz) and <=0.5ulp otherwise: per-element error ~2e-7
            // with random sign -> invisible in a 4M-term sum at 1e-3 tol.
            float q = m[k] ? p[k] : 1.0f - p[k];
            s += logf(q);
        }
    } else {
        // Generic fallback (any n).
        #pragma unroll 4
        for (int i = tid; i < n; i += stride) {
            float p = __ldg(&pred[(size_t)i * 8]);
            s += mask[i] ? logf(p) : log1pf(-p);
        }
    }

    // Warp reduction.
    #pragma unroll
    for (int o = 16; o > 0; o >>= 1)
        s += __shfl_xor_sync(0xFFFFFFFFu, s, o);

    __shared__ float warp_sums[TPB / 32];
    const int lane = threadIdx.x & 31;
    const int warp = threadIdx.x >> 5;
    if (lane == 0) warp_sums[warp] = s;
    __syncthreads();

    if (warp == 0) {
        float bs = (lane < (TPB >> 5)) ? warp_sums[lane] : 0.0f;
        #pragma unroll
        for (int o = 4; o > 0; o >>= 1)
            bs += __shfl_xor_sync(0xFFFFFFFFu, bs, o);
        if (lane == 0) g_part[blockIdx.x] = bs;
    }

    // Elect the last block to finish (threadfence-reduction pattern).
    __shared__ bool is_last;
    __threadfence();
    if (threadIdx.x == 0) {
        unsigned int c = atomicAdd(&g_count, 1u);
        is_last = (c == gridDim.x - 1);
    }
    __syncthreads();

    if (is_last) {
        double d = 0.0;
        for (int i = threadIdx.x; i < (int)gridDim.x; i += TPB)
            d += (double)g_part[i];

        #pragma unroll
        for (int o = 16; o > 0; o >>= 1)
            d += __shfl_xor_sync(0xFFFFFFFFu, d, o);

        __shared__ double dwarp[TPB / 32];
        if (lane == 0) dwarp[warp] = d;
        __syncthreads();
        if (warp == 0) {
            double bd = (lane < (TPB >> 5)) ? dwarp[lane] : 0.0;
            #pragma unroll
            for (int o = 4; o > 0; o >>= 1)
                bd += __shfl_xor_sync(0xFFFFFFFFu, bd, o);
            if (lane == 0) {
                out[0] = (float)(-bd * (1.0 / 256.0));
                g_count = 0;  // self-reset for next graph replay
            }
        }
    }
}

extern "C" void kernel_launch(void* const* d_in, const int* in_sizes, int n_in,
                              void* d_out, int out_size)
{
    const float* pred = (const float*)d_in[0];
    const unsigned char* mask = (const unsigned char*)d_in[1];
    float* out = (float*)d_out;

    int n = in_sizes[1];                             // 4,194,304 expected

    int blocks = (n + TPB * ILP - 1) / (TPB * ILP);  // 1024 for n=4M
    if (blocks > MAX_BLOCKS) blocks = MAX_BLOCKS;    // fallback path handles rest
    if (blocks < 1) blocks = 1;

    nll_fused_kernel<<<blocks, TPB>>>(pred, mask, out, n);
}